// round 3
// baseline (speedup 1.0000x reference)
#include <cuda_runtime.h>

#define NB 64
#define NC 3
#define NH 256
#define NW 256

struct AugParams {
    int   doFlip, doTrans, th, tw, doCut;
    int   cx0, cx1, cy0, cy1;
    float brightAdd, contrastMul;
};

__global__ __launch_bounds__(256)
void diffaug_kernel(const float* __restrict__ x,
                    const float* __restrict__ p_,
                    const float* __restrict__ flip_u,
                    const float* __restrict__ bright_n,
                    const float* __restrict__ bright_u,
                    const float* __restrict__ contrast_n,
                    const float* __restrict__ contrast_u,
                    const int*   __restrict__ trans_h,
                    const int*   __restrict__ trans_w,
                    const float* __restrict__ trans_u,
                    const int*   __restrict__ cut_ox,
                    const int*   __restrict__ cut_oy,
                    const float* __restrict__ cut_u,
                    float* __restrict__ out)
{
    __shared__ AugParams P;

    // grid: NB * NC * (NH/4) blocks; each block = 4 rows of one (b, c) plane.
    const int blk    = blockIdx.x;
    const int b      = blk / (NC * (NH / 4));
    const int rem    = blk % (NC * (NH / 4));
    const int c      = rem / (NH / 4);
    const int rowblk = rem % (NH / 4);

    if (threadIdx.x == 0) {
        const float p = p_[0];
        P.doFlip      = flip_u[b] < 0.5f * p;
        P.brightAdd   = (bright_u[b]   < p) ? bright_n[b] * 0.2f : 0.0f;
        P.contrastMul = (contrast_u[b] < p) ? exp2f(contrast_n[b] * 0.5f) : 1.0f;
        P.doTrans     = trans_u[b] < p;
        P.th          = trans_h[b];
        P.tw          = trans_w[b];
        P.doCut       = cut_u[b] < p;
        const int ox = cut_ox[b], oy = cut_oy[b];
        P.cx0 = max(0, ox - 64); P.cx1 = min(NH - 1, ox + 63);
        P.cy0 = max(0, oy - 64); P.cy1 = min(NW - 1, oy + 63);
    }
    __syncthreads();

    const int h  = rowblk * 4 + (int)(threadIdx.x >> 6);   // 4 rows per block
    const int w0 = ((int)threadIdx.x & 63) * 4;            // 64 float4 lanes per row

    const size_t plane = (size_t)(b * NC + c) * (NH * NW);
    const float* base  = x + plane;

    // ---- translation row index (pad rows -> exact zero) ----
    int  srcH = h;
    bool pad  = false;
    if (P.doTrans) {
        int gh = h + P.th + 1;
        gh   = min(max(gh, 0), NH + 1);
        pad  = (gh == 0) || (gh == NH + 1);
        srcH = min(max(gh - 1, 0), NH - 1);          // clamped; unused when pad
    }
    const float* row = base + srcH * NW;

    const bool rowInCut = P.doCut && (h >= P.cx0) && (h <= P.cx1);

    float v[4];
#pragma unroll
    for (int i = 0; i < 4; i++) {
        const int w = w0 + i;
        int srcW = w;
        if (P.doTrans) {
            int t = w + P.tw;                        // [-16, 271]
            if (t < 0)            t += (NW - 1);     // mod (W-1)=255, python semantics
            else if (t >= NW - 1) t -= (NW - 1);
            srcW = t;
        }
        if (P.doFlip) srcW = NW - 1 - srcW;

        float val = pad ? 0.0f
                        : (__ldg(row + srcW) + P.brightAdd) * P.contrastMul;
        if (rowInCut && (w >= P.cy0) && (w <= P.cy1)) val = 0.0f;
        v[i] = val;
    }

    *reinterpret_cast<float4*>(out + plane + (size_t)h * NW + w0) =
        make_float4(v[0], v[1], v[2], v[3]);
}

extern "C" void kernel_launch(void* const* d_in, const int* in_sizes, int n_in,
                              void* d_out, int out_size)
{
    (void)in_sizes; (void)n_in; (void)out_size;
    const float* x          = (const float*)d_in[0];
    const float* p          = (const float*)d_in[1];
    const float* flip_u     = (const float*)d_in[2];
    const float* bright_n   = (const float*)d_in[3];
    const float* bright_u   = (const float*)d_in[4];
    const float* contrast_n = (const float*)d_in[5];
    const float* contrast_u = (const float*)d_in[6];
    const int*   trans_h    = (const int*)d_in[7];
    const int*   trans_w    = (const int*)d_in[8];
    const float* trans_u    = (const float*)d_in[9];
    const int*   cut_ox     = (const int*)d_in[10];
    const int*   cut_oy     = (const int*)d_in[11];
    const float* cut_u      = (const float*)d_in[12];
    float*       out        = (float*)d_out;

    const dim3 grid(NB * NC * (NH / 4));
    const dim3 block(256);
    diffaug_kernel<<<grid, block>>>(x, p, flip_u, bright_n, bright_u,
                                    contrast_n, contrast_u, trans_h, trans_w,
                                    trans_u, cut_ox, cut_oy, cut_u, out);
}

// round 4
// speedup vs baseline: 1.1636x; 1.1636x over previous
#include <cuda_runtime.h>

#define NB 64
#define NC 3
#define NH 256
#define NW 256

struct AugParams {
    int   doTrans, tw, doCut;
    int   th_off;          // trans_h + 1, pre-added
    int   cx0, cx1, cy0, cySpan;
    int   flipOff, flipSign;   // srcW = flipOff + flipSign * t
    float contrastMul, addTerm; // val = fma(x, contrastMul, addTerm)
};

__global__ __launch_bounds__(256)
void diffaug_kernel(const float* __restrict__ x,
                    const float* __restrict__ p_,
                    const float* __restrict__ flip_u,
                    const float* __restrict__ bright_n,
                    const float* __restrict__ bright_u,
                    const float* __restrict__ contrast_n,
                    const float* __restrict__ contrast_u,
                    const int*   __restrict__ trans_h,
                    const int*   __restrict__ trans_w,
                    const float* __restrict__ trans_u,
                    const int*   __restrict__ cut_ox,
                    const int*   __restrict__ cut_oy,
                    const float* __restrict__ cut_u,
                    float* __restrict__ out)
{
    __shared__ AugParams P;

    // grid: NB * NC * (NH/4) blocks; each block = 4 rows of one (b, c) plane.
    const int blk    = blockIdx.x;
    const int b      = blk / (NC * (NH / 4));
    const int rem    = blk % (NC * (NH / 4));
    const int c      = rem / (NH / 4);
    const int rowblk = rem % (NH / 4);

    if (threadIdx.x == 0) {
        const float p = p_[0];
        const bool doFlip = flip_u[b] < 0.5f * p;
        const float brightAdd = (bright_u[b] < p) ? bright_n[b] * 0.2f : 0.0f;
        const float cm = (contrast_u[b] < p) ? exp2f(contrast_n[b] * 0.5f) : 1.0f;
        P.contrastMul = cm;
        P.addTerm     = brightAdd * cm;
        P.doTrans     = trans_u[b] < p;
        P.th_off      = trans_h[b] + 1;
        P.tw          = trans_w[b];
        P.doCut       = cut_u[b] < p;
        P.flipOff     = doFlip ? (NW - 1) : 0;
        P.flipSign    = doFlip ? -1 : 1;
        const int ox = cut_ox[b], oy = cut_oy[b];
        P.cx0 = max(0, ox - 64); P.cx1 = min(NH - 1, ox + 63);
        P.cy0 = max(0, oy - 64);
        P.cySpan = min(NW - 1, oy + 63) - P.cy0;   // >= 0 always (clamp overlap)
    }
    __syncthreads();

    const int h    = rowblk * 4 + (int)(threadIdx.x >> 6);  // one row per warp
    const int lane = (int)threadIdx.x & 63;

    const size_t plane = (size_t)(b * NC + c) * (NH * NW);
    float* orow = out + plane + (size_t)h * NW;

    // ---- translation row index (pad rows -> exact zero), warp-uniform ----
    int srcH = h;
    if (P.doTrans) {
        int gh = h + P.th_off;
        gh = min(max(gh, 0), NH + 1);
        if (gh == 0 || gh == NH + 1) {               // pad row: pure zeros
#pragma unroll
            for (int i = 0; i < 4; i++) orow[lane + i * 64] = 0.0f;
            return;
        }
        srcH = gh - 1;
    }
    const float* row = x + plane + (size_t)srcH * NW;

    const float cm = P.contrastMul;
    const float ad = P.addTerm;
    const bool  rowInCut = P.doCut && (h >= P.cx0) && (h <= P.cx1);
    const int   cy0 = P.cy0, cySpan = P.cySpan;
    const int   fOff = P.flipOff, fSign = P.flipSign;
    const int   doT = P.doTrans, tw = P.tw;

#pragma unroll
    for (int i = 0; i < 4; i++) {
        const int w = lane + i * 64;
        int t = w;
        if (doT) {
            t = w + tw;                              // [-16, 271]
            if (t < 0)            t += (NW - 1);     // mod (W-1)=255
            else if (t >= NW - 1) t -= (NW - 1);
        }
        const int srcW = fOff + fSign * t;           // flip fold: 1 IMAD

        float val = fmaf(__ldg(row + srcW), cm, ad);
        if (rowInCut && (unsigned)(w - cy0) <= (unsigned)cySpan) val = 0.0f;
        orow[w] = val;
    }
}

extern "C" void kernel_launch(void* const* d_in, const int* in_sizes, int n_in,
                              void* d_out, int out_size)
{
    (void)in_sizes; (void)n_in; (void)out_size;
    const float* x          = (const float*)d_in[0];
    const float* p          = (const float*)d_in[1];
    const float* flip_u     = (const float*)d_in[2];
    const float* bright_n   = (const float*)d_in[3];
    const float* bright_u   = (const float*)d_in[4];
    const float* contrast_n = (const float*)d_in[5];
    const float* contrast_u = (const float*)d_in[6];
    const int*   trans_h    = (const int*)d_in[7];
    const int*   trans_w    = (const int*)d_in[8];
    const float* trans_u    = (const float*)d_in[9];
    const int*   cut_ox     = (const int*)d_in[10];
    const int*   cut_oy     = (const int*)d_in[11];
    const float* cut_u      = (const float*)d_in[12];
    float*       out        = (float*)d_out;

    const dim3 grid(NB * NC * (NH / 4));
    const dim3 block(256);
    diffaug_kernel<<<grid, block>>>(x, p, flip_u, bright_n, bright_u,
                                    contrast_n, contrast_u, trans_h, trans_w,
                                    trans_u, cut_ox, cut_oy, cut_u, out);
}

// round 7
// speedup vs baseline: 1.1751x; 1.0099x over previous
#include <cuda_runtime.h>

#define NB 64
#define NC 3
#define NH 256
#define NW 256

struct AugParams {
    int   doTrans, doFlip, doCut;
    int   tw, th_off;               // th_off = trans_h + 1
    int   cx0, cx1, cy0, cySpan;
    float cm, ad;                   // val = fma(x, cm, ad)
};

__global__ __launch_bounds__(256)
void diffaug_kernel(const float* __restrict__ x,
                    const float* __restrict__ p_,
                    const float* __restrict__ flip_u,
                    const float* __restrict__ bright_n,
                    const float* __restrict__ bright_u,
                    const float* __restrict__ contrast_n,
                    const float* __restrict__ contrast_u,
                    const int*   __restrict__ trans_h,
                    const int*   __restrict__ trans_w,
                    const float* __restrict__ trans_u,
                    const int*   __restrict__ cut_ox,
                    const int*   __restrict__ cut_oy,
                    const float* __restrict__ cut_u,
                    float* __restrict__ out)
{
    __shared__ AugParams P;
    // 16B-aligned: float4 staging stores require it (row stride 288*4=1152B is 16B-multiple)
    __shared__ __align__(16) float s[4][288];  // [0:16) left halo, [16:272) row, [272:288) right halo

    // grid: NB * NC * (NH/4) blocks; each block = 4 rows of one (b, c) plane.
    const int blk    = blockIdx.x;
    const int b      = blk / (NC * (NH / 4));
    const int rem    = blk % (NC * (NH / 4));
    const int c      = rem / (NH / 4);
    const int rowblk = rem % (NH / 4);

    if (threadIdx.x == 0) {
        const float p = p_[0];
        const float ba = (bright_u[b] < p) ? bright_n[b] * 0.2f : 0.0f;
        const float cm = (contrast_u[b] < p) ? exp2f(contrast_n[b] * 0.5f) : 1.0f;
        P.cm      = cm;
        P.ad      = ba * cm;
        P.doFlip  = flip_u[b] < 0.5f * p;
        P.doTrans = trans_u[b] < p;
        P.th_off  = trans_h[b] + 1;
        P.tw      = trans_w[b];
        P.doCut   = cut_u[b] < p;
        const int ox = cut_ox[b], oy = cut_oy[b];
        P.cx0 = max(0, ox - 64); P.cx1 = min(NH - 1, ox + 63);
        P.cy0 = max(0, oy - 64);
        P.cySpan = min(NW - 1, oy + 63) - P.cy0;
    }
    __syncthreads();

    const int row = (int)(threadIdx.x >> 6);       // 0..3
    const int t   = (int)(threadIdx.x & 63);       // 0..63
    const int h   = rowblk * 4 + row;

    const size_t plane = (size_t)(b * NC + c) * (NH * NW);
    float* orow = out + plane + (size_t)h * NW;

    const float cm = P.cm, ad = P.ad;
    const bool  rowInCut = P.doCut && (h >= P.cx0) && (h <= P.cx1);
    const int   cy0 = P.cy0, cySpan = P.cySpan;
    const int   j4 = 4 * t;

    if (!P.doTrans) {
        // ---------- Path A: fully vectorized copy (+optional mirror) ----------
        const int gj = P.doFlip ? (252 - j4) : j4;
        const float4 v = *reinterpret_cast<const float4*>(x + plane + (size_t)h * NW + gj);
        float a0, a1, a2, a3;
        if (P.doFlip) { a0 = v.w; a1 = v.z; a2 = v.y; a3 = v.x; }
        else          { a0 = v.x; a1 = v.y; a2 = v.z; a3 = v.w; }
        a0 = fmaf(a0, cm, ad); a1 = fmaf(a1, cm, ad);
        a2 = fmaf(a2, cm, ad); a3 = fmaf(a3, cm, ad);
        if (rowInCut) {
            if ((unsigned)(j4     - cy0) <= (unsigned)cySpan) a0 = 0.0f;
            if ((unsigned)(j4 + 1 - cy0) <= (unsigned)cySpan) a1 = 0.0f;
            if ((unsigned)(j4 + 2 - cy0) <= (unsigned)cySpan) a2 = 0.0f;
            if ((unsigned)(j4 + 3 - cy0) <= (unsigned)cySpan) a3 = 0.0f;
        }
        *reinterpret_cast<float4*>(orow + j4) = make_float4(a0, a1, a2, a3);
        return;
    }

    // ---------- Path B: translation via SMEM-staged row with wrap halo ----------
    int gh = h + P.th_off;
    gh = min(max(gh, 0), NH + 1);
    const bool pad  = (gh == 0) || (gh == NH + 1);
    const int  srcH = min(max(gh - 1, 0), NH - 1);

    if (!pad) {
        // stage flipped source row linearly: s[row][16+j] = frow[j]
        const int gj = P.doFlip ? (252 - j4) : j4;
        const float4 v = *reinterpret_cast<const float4*>(x + plane + (size_t)srcH * NW + gj);
        float4 w4;
        if (P.doFlip) { w4.x = v.w; w4.y = v.z; w4.z = v.y; w4.w = v.x; }
        else          { w4 = v; }
        *reinterpret_cast<float4*>(&s[row][16 + j4]) = w4;
    }
    __syncthreads();

    // halo: right needs 17 (w+tw up to 271 -> frow[0..16]); left needs 16 (w+tw >= -16 -> frow[239..254])
    if (threadIdx.x < 132) {
        const int r = (int)threadIdx.x / 33;
        const int q = (int)threadIdx.x % 33;
        if (q < 17) s[r][271 + q] = s[r][16 + q];         // s[16+255+k] = frow[k]
        else        s[r][q - 17]  = s[r][255 + (q - 17)]; // s[m] = frow[239+m]
    }
    __syncthreads();

    if (pad) {
#pragma unroll
        for (int i = 0; i < 4; i++) orow[t + 64 * i] = 0.0f;
        return;
    }

    const int base = 16 + P.tw + t;                      // in [0, 32+63], all accesses in-range
#pragma unroll
    for (int i = 0; i < 4; i++) {
        const int w = t + 64 * i;
        float val = fmaf(s[row][base + 64 * i], cm, ad);
        if (rowInCut && (unsigned)(w - cy0) <= (unsigned)cySpan) val = 0.0f;
        orow[w] = val;
    }
}

extern "C" void kernel_launch(void* const* d_in, const int* in_sizes, int n_in,
                              void* d_out, int out_size)
{
    (void)in_sizes; (void)n_in; (void)out_size;
    const float* x          = (const float*)d_in[0];
    const float* p          = (const float*)d_in[1];
    const float* flip_u     = (const float*)d_in[2];
    const float* bright_n   = (const float*)d_in[3];
    const float* bright_u   = (const float*)d_in[4];
    const float* contrast_n = (const float*)d_in[5];
    const float* contrast_u = (const float*)d_in[6];
    const int*   trans_h    = (const int*)d_in[7];
    const int*   trans_w    = (const int*)d_in[8];
    const float* trans_u    = (const float*)d_in[9];
    const int*   cut_ox     = (const int*)d_in[10];
    const int*   cut_oy     = (const int*)d_in[11];
    const float* cut_u      = (const float*)d_in[12];
    float*       out        = (float*)d_out;

    const dim3 grid(NB * NC * (NH / 4));
    const dim3 block(256);
    diffaug_kernel<<<grid, block>>>(x, p, flip_u, bright_n, bright_u,
                                    contrast_n, contrast_u, trans_h, trans_w,
                                    trans_u, cut_ox, cut_oy, cut_u, out);
}

// round 9
// speedup vs baseline: 1.4444x; 1.2292x over previous
#include <cuda_runtime.h>

#define NB 64
#define NC 3
#define NH 256
#define NW 256
#define RPB 16                      // rows per block
#define KR 4                        // rows per thread

struct AugParams {
    int   doTrans, doFlip, doCut;
    int   tw, th_off;               // th_off = trans_h + 1
    int   cx0, cx1, cy0, cySpan;
    float cm, ad;                   // val = fma(x, cm, ad)
};

__global__ __launch_bounds__(256)
void diffaug_kernel(const float* __restrict__ x,
                    const float* __restrict__ p_,
                    const float* __restrict__ flip_u,
                    const float* __restrict__ bright_n,
                    const float* __restrict__ bright_u,
                    const float* __restrict__ contrast_n,
                    const float* __restrict__ contrast_u,
                    const int*   __restrict__ trans_h,
                    const int*   __restrict__ trans_w,
                    const float* __restrict__ trans_u,
                    const int*   __restrict__ cut_ox,
                    const int*   __restrict__ cut_oy,
                    const float* __restrict__ cut_u,
                    float* __restrict__ out)
{
    __shared__ AugParams P;
    // 16B-aligned: float4 staging stores; row stride 288*4B is a 16B multiple.
    __shared__ __align__(16) float s[RPB][288]; // [0:16) left halo, [16:272) row, [272:288) right halo

    // grid: NB * NC * (NH/RPB) blocks; each block = RPB rows of one (b, c) plane.
    const int blk  = blockIdx.x;
    const int b    = blk / (NC * (NH / RPB));
    const int rem  = blk % (NC * (NH / RPB));
    const int c    = rem / (NH / RPB);
    const int slab = rem % (NH / RPB);
    const int h0   = slab * RPB;

    if (threadIdx.x == 0) {
        const float p = p_[0];
        const float ba = (bright_u[b] < p) ? bright_n[b] * 0.2f : 0.0f;
        const float cm = (contrast_u[b] < p) ? exp2f(contrast_n[b] * 0.5f) : 1.0f;
        P.cm      = cm;
        P.ad      = ba * cm;
        P.doFlip  = flip_u[b] < 0.5f * p;
        P.doTrans = trans_u[b] < p;
        P.th_off  = trans_h[b] + 1;
        P.tw      = trans_w[b];
        P.doCut   = cut_u[b] < p;
        const int ox = cut_ox[b], oy = cut_oy[b];
        P.cx0 = max(0, ox - 64); P.cx1 = min(NH - 1, ox + 63);
        P.cy0 = max(0, oy - 64);
        P.cySpan = min(NW - 1, oy + 63) - P.cy0;
    }
    __syncthreads();

    const int rg = (int)(threadIdx.x >> 6);        // 0..3 row group
    const int t  = (int)(threadIdx.x & 63);        // 0..63
    const int j4 = 4 * t;

    const size_t plane = (size_t)(b * NC + c) * (NH * NW);
    const float* xpl = x + plane;
    float*       opl = out + plane;

    const float cm = P.cm, ad = P.ad;
    const int   cy0 = P.cy0, cySpan = P.cySpan;
    const int   gj  = P.doFlip ? (252 - j4) : j4;
    const bool  flip = P.doFlip;

    if (!P.doTrans) {
        // ---------- Path A: vectorized copy (+optional mirror), MLP=4 ----------
        float4 v[KR];
#pragma unroll
        for (int k = 0; k < KR; k++) {
            const int h = h0 + rg + 4 * k;
            v[k] = *reinterpret_cast<const float4*>(xpl + (size_t)h * NW + gj);
        }
#pragma unroll
        for (int k = 0; k < KR; k++) {
            const int h = h0 + rg + 4 * k;
            float a0, a1, a2, a3;
            if (flip) { a0 = v[k].w; a1 = v[k].z; a2 = v[k].y; a3 = v[k].x; }
            else      { a0 = v[k].x; a1 = v[k].y; a2 = v[k].z; a3 = v[k].w; }
            a0 = fmaf(a0, cm, ad); a1 = fmaf(a1, cm, ad);
            a2 = fmaf(a2, cm, ad); a3 = fmaf(a3, cm, ad);
            if (P.doCut && (h >= P.cx0) && (h <= P.cx1)) {
                if ((unsigned)(j4     - cy0) <= (unsigned)cySpan) a0 = 0.0f;
                if ((unsigned)(j4 + 1 - cy0) <= (unsigned)cySpan) a1 = 0.0f;
                if ((unsigned)(j4 + 2 - cy0) <= (unsigned)cySpan) a2 = 0.0f;
                if ((unsigned)(j4 + 3 - cy0) <= (unsigned)cySpan) a3 = 0.0f;
            }
            *reinterpret_cast<float4*>(opl + (size_t)h * NW + j4) =
                make_float4(a0, a1, a2, a3);
        }
        return;
    }

    // ---------- Path B: translation via SMEM-staged rows with wrap halo ----------
    bool pad[KR];
#pragma unroll
    for (int k = 0; k < KR; k++) {
        const int h  = h0 + rg + 4 * k;
        int gh = h + P.th_off;
        gh = min(max(gh, 0), NH + 1);
        pad[k] = (gh == 0) || (gh == NH + 1);
        const int srcH = min(max(gh - 1, 0), NH - 1);
        if (!pad[k]) {
            const float4 v = *reinterpret_cast<const float4*>(xpl + (size_t)srcH * NW + gj);
            float4 w4;
            if (flip) { w4.x = v.w; w4.y = v.z; w4.z = v.y; w4.w = v.x; }
            else      { w4 = v; }
            *reinterpret_cast<float4*>(&s[rg + 4 * k][16 + j4]) = w4;
        }
    }
    __syncthreads();

    // halo: right 17 (frow[0..16] -> s[271..287]); left 16 (frow[239..254] -> s[0..15])
    for (int idx = (int)threadIdx.x; idx < RPB * 33; idx += 256) {
        const int r = idx / 33;
        const int q = idx % 33;
        if (q < 17) s[r][271 + q] = s[r][16 + q];
        else        s[r][q - 17]  = s[r][255 + (q - 17)];
    }
    __syncthreads();

    const int base = 16 + P.tw + t;                // in-range for all accesses
#pragma unroll
    for (int k = 0; k < KR; k++) {
        const int h = h0 + rg + 4 * k;
        float* orow = opl + (size_t)h * NW;
        if (pad[k]) {
#pragma unroll
            for (int i = 0; i < 4; i++) orow[t + 64 * i] = 0.0f;
            continue;
        }
        const bool rowInCut = P.doCut && (h >= P.cx0) && (h <= P.cx1);
#pragma unroll
        for (int i = 0; i < 4; i++) {
            const int w = t + 64 * i;
            float val = fmaf(s[rg + 4 * k][base + 64 * i], cm, ad);
            if (rowInCut && (unsigned)(w - cy0) <= (unsigned)cySpan) val = 0.0f;
            orow[w] = val;
        }
    }
}

extern "C" void kernel_launch(void* const* d_in, const int* in_sizes, int n_in,
                              void* d_out, int out_size)
{
    (void)in_sizes; (void)n_in; (void)out_size;
    const float* x          = (const float*)d_in[0];
    const float* p          = (const float*)d_in[1];
    const float* flip_u     = (const float*)d_in[2];
    const float* bright_n   = (const float*)d_in[3];
    const float* bright_u   = (const float*)d_in[4];
    const float* contrast_n = (const float*)d_in[5];
    const float* contrast_u = (const float*)d_in[6];
    const int*   trans_h    = (const int*)d_in[7];
    const int*   trans_w    = (const int*)d_in[8];
    const float* trans_u    = (const float*)d_in[9];
    const int*   cut_ox     = (const int*)d_in[10];
    const int*   cut_oy     = (const int*)d_in[11];
    const float* cut_u      = (const float*)d_in[12];
    float*       out        = (float*)d_out;

    const dim3 grid(NB * NC * (NH / RPB));
    const dim3 block(256);
    diffaug_kernel<<<grid, block>>>(x, p, flip_u, bright_n, bright_u,
                                    contrast_n, contrast_u, trans_h, trans_w,
                                    trans_u, cut_ox, cut_oy, cut_u, out);
}